// round 3
// baseline (speedup 1.0000x reference)
#include <cuda_runtime.h>

// Global accumulators (zero-initialized at module load; reset by the last
// block of every run so graph replays are deterministic). No device allocs.
__device__ double g_sum0;                  // sum of picked log-probs, class 0
__device__ double g_sum1;                  // sum of picked log-probs, class 1
__device__ unsigned long long g_cnt1;      // count of targets == 1
__device__ unsigned int g_blocks_done;     // retirement counter

__device__ __forceinline__ void proc_token(float x0, float x1, int t,
                                           float& s0, float& s1, int& c1) {
    // picked log-softmax value: x[t] - logsumexp(x0, x1)
    float m   = fmaxf(x0, x1);
    float d   = -fabsf(x0 - x1);
    float lse = m + __logf(1.0f + __expf(d));
    if (t != 0) {
        s1 += x1 - lse;
        c1 += 1;
    } else {
        s0 += x0 - lse;
    }
}

// One fused kernel: per-block dtype detection + reduction + last-block finalize.
// Each thread: 8 tokens = 4x float4 (x) + 2x int4 (targets-as-int32, speculative).
__global__ __launch_bounds__(256) void nll_fused_kernel(
    const float* __restrict__ x,
    const void* __restrict__ targets,
    long long n_tokens,
    float* __restrict__ out)
{
    const long long tid  = (long long)blockIdx.x * blockDim.x + threadIdx.x;
    const long long base = tid * 8;   // first token for this thread
    const bool full = (base + 7 < n_tokens);

    float s0 = 0.0f, s1 = 0.0f;
    int   c1 = 0;

    float4 a0, a1, a2, a3;
    int w[8] = {0, 0, 0, 0, 0, 0, 0, 0};

    if (full) {
        const float4* x4 = reinterpret_cast<const float4*>(x) + base / 2;
        a0 = x4[0];
        a1 = x4[1];
        a2 = x4[2];
        a3 = x4[3];
        // Speculative int32-layout target load (in-bounds under BOTH layouts:
        // word indices < n_tokens <= #words).
        const int4* t4 = reinterpret_cast<const int4*>(targets) + base / 4;
        int4 b0 = t4[0];
        int4 b1 = t4[1];
        w[0] = b0.x; w[1] = b0.y; w[2] = b0.z; w[3] = b0.w;
        w[4] = b1.x; w[5] = b1.y; w[6] = b1.z; w[7] = b1.w;
    }

    // Layout vote: int64 targets in {0,1} have all odd 32-bit words == 0.
    // 2048 words per block -> misdetect prob ~2^-1024 for random int32 targets.
    int pred = ((w[1] | w[3] | w[5] | w[7]) != 0) ? 1 : 0;
    int mode32 = __syncthreads_or(pred);

    if (full) {
        if (!mode32) {
            // int64 layout: reload the correct bytes.
            const ulonglong2* t2 = reinterpret_cast<const ulonglong2*>(targets) + base / 2;
            ulonglong2 c0 = t2[0];
            ulonglong2 c2 = t2[1];
            ulonglong2 c4 = t2[2];
            ulonglong2 c6 = t2[3];
            w[0] = (int)c0.x; w[1] = (int)c0.y;
            w[2] = (int)c2.x; w[3] = (int)c2.y;
            w[4] = (int)c4.x; w[5] = (int)c4.y;
            w[6] = (int)c6.x; w[7] = (int)c6.y;
        }
        proc_token(a0.x, a0.y, w[0], s0, s1, c1);
        proc_token(a0.z, a0.w, w[1], s0, s1, c1);
        proc_token(a1.x, a1.y, w[2], s0, s1, c1);
        proc_token(a1.z, a1.w, w[3], s0, s1, c1);
        proc_token(a2.x, a2.y, w[4], s0, s1, c1);
        proc_token(a2.z, a2.w, w[5], s0, s1, c1);
        proc_token(a3.x, a3.y, w[6], s0, s1, c1);
        proc_token(a3.z, a3.w, w[7], s0, s1, c1);
    } else {
        // Tail (only if n_tokens % 2048 != 0 for some block).
        for (long long i = base; i < n_tokens && i < base + 8; i++) {
            int ti;
            if (!mode32) ti = (int)reinterpret_cast<const long long*>(targets)[i];
            else         ti = reinterpret_cast<const int*>(targets)[i];
            proc_token(x[2 * i], x[2 * i + 1], ti, s0, s1, c1);
        }
    }

    // warp reduction
    #pragma unroll
    for (int off = 16; off > 0; off >>= 1) {
        s0 += __shfl_down_sync(0xFFFFFFFFu, s0, off);
        s1 += __shfl_down_sync(0xFFFFFFFFu, s1, off);
        c1 += __shfl_down_sync(0xFFFFFFFFu, c1, off);
    }

    __shared__ float sh0[8];
    __shared__ float sh1[8];
    __shared__ int   shc[8];
    const int lane = threadIdx.x & 31;
    const int wid  = threadIdx.x >> 5;
    if (lane == 0) { sh0[wid] = s0; sh1[wid] = s1; shc[wid] = c1; }
    __syncthreads();

    __shared__ bool is_last;
    if (wid == 0) {
        const int nw = blockDim.x >> 5;
        s0 = (lane < nw) ? sh0[lane] : 0.0f;
        s1 = (lane < nw) ? sh1[lane] : 0.0f;
        c1 = (lane < nw) ? shc[lane] : 0;
        #pragma unroll
        for (int off = 4; off > 0; off >>= 1) {
            s0 += __shfl_down_sync(0xFFFFFFFFu, s0, off);
            s1 += __shfl_down_sync(0xFFFFFFFFu, s1, off);
            c1 += __shfl_down_sync(0xFFFFFFFFu, c1, off);
        }
        if (lane == 0) {
            atomicAdd(&g_sum0, (double)s0);
            atomicAdd(&g_sum1, (double)s1);
            atomicAdd(&g_cnt1, (unsigned long long)c1);
            __threadfence();
            unsigned int done = atomicAdd(&g_blocks_done, 1u);
            is_last = (done == gridDim.x - 1u);
        }
    }
    __syncthreads();

    // Last block to retire finalizes and resets globals for the next replay.
    if (is_last && threadIdx.x == 0) {
        __threadfence();
        double sum0 = g_sum0;
        double sum1 = g_sum1;
        unsigned long long n1 = g_cnt1;
        unsigned long long n0 = (unsigned long long)n_tokens - n1;
        double r = (n1 > 0) ? (-sum1 / (double)n1) : 0.0;
        double p = (n0 > 0) ? (-sum0 / (double)n0) : 0.0;
        out[0] = (float)(p + r);
        // reset for next graph replay
        g_sum0 = 0.0;
        g_sum1 = 0.0;
        g_cnt1 = 0ull;
        g_blocks_done = 0u;
    }
}

extern "C" void kernel_launch(void* const* d_in, const int* in_sizes, int n_in,
                              void* d_out, int out_size) {
    const float* x       = (const float*)d_in[0];
    const void*  targets = d_in[1];
    float*       out     = (float*)d_out;

    const long long n_tokens = (long long)in_sizes[1];

    const long long threads_needed = (n_tokens + 7) / 8;
    const int block = 256;
    const int grid  = (int)((threads_needed + block - 1) / block);
    nll_fused_kernel<<<grid, block>>>(x, targets, n_tokens, out);
}

// round 4
// speedup vs baseline: 1.2729x; 1.2729x over previous
#include <cuda_runtime.h>

// Global accumulators (zero-initialized at module load; reset by the last
// block of every run so graph replays are deterministic). No device allocs.
__device__ double g_sum0;                  // sum of picked log-probs, class 0
__device__ double g_sum1;                  // sum of picked log-probs, class 1
__device__ unsigned long long g_cnt1;      // count of targets == 1
__device__ unsigned int g_blocks_done;     // retirement counter

__device__ __forceinline__ void proc_token(float x0, float x1, int t,
                                           float& s0, float& s1, int& c1) {
    // picked log-softmax value: x[t] - logsumexp(x0, x1)
    float m   = fmaxf(x0, x1);
    float d   = -fabsf(x0 - x1);
    float lse = m + __logf(1.0f + __expf(d));
    if (t != 0) {
        s1 += x1 - lse;
        c1 += 1;
    } else {
        s0 += x0 - lse;
    }
}

// Single fused kernel. Targets are int32 (established: 64-bit-stride reads
// OOB-faulted in R1; runtime detection picked int32 in R2/R3).
// Each thread: 8 tokens = 4x float4 (x) + 2x int4 (targets), all 128-bit
// loads front-batched for high MLP. No barriers before compute.
__global__ __launch_bounds__(256) void nll_fused_kernel(
    const float* __restrict__ x,
    const int* __restrict__ targets,
    long long n_tokens,
    float* __restrict__ out)
{
    const long long tid  = (long long)blockIdx.x * blockDim.x + threadIdx.x;
    const long long base = tid * 8;   // first token for this thread

    float s0 = 0.0f, s1 = 0.0f;
    int   c1 = 0;

    if (base + 7 < n_tokens) {
        const float4* x4 = reinterpret_cast<const float4*>(x) + base / 2;
        const int4*   t4 = reinterpret_cast<const int4*>(targets) + base / 4;
        // front-batch all 6 128-bit loads
        float4 a0 = x4[0];
        float4 a1 = x4[1];
        float4 a2 = x4[2];
        float4 a3 = x4[3];
        int4   b0 = t4[0];
        int4   b1 = t4[1];

        proc_token(a0.x, a0.y, b0.x, s0, s1, c1);
        proc_token(a0.z, a0.w, b0.y, s0, s1, c1);
        proc_token(a1.x, a1.y, b0.z, s0, s1, c1);
        proc_token(a1.z, a1.w, b0.w, s0, s1, c1);
        proc_token(a2.x, a2.y, b1.x, s0, s1, c1);
        proc_token(a2.z, a2.w, b1.y, s0, s1, c1);
        proc_token(a3.x, a3.y, b1.z, s0, s1, c1);
        proc_token(a3.z, a3.w, b1.w, s0, s1, c1);
    } else {
        // tail (only hit if n_tokens % 2048 != 0)
        for (long long i = base; i < n_tokens && i < base + 8; i++) {
            proc_token(x[2 * i], x[2 * i + 1], targets[i], s0, s1, c1);
        }
    }

    // warp reduction
    #pragma unroll
    for (int off = 16; off > 0; off >>= 1) {
        s0 += __shfl_down_sync(0xFFFFFFFFu, s0, off);
        s1 += __shfl_down_sync(0xFFFFFFFFu, s1, off);
        c1 += __shfl_down_sync(0xFFFFFFFFu, c1, off);
    }

    __shared__ float sh0[8];
    __shared__ float sh1[8];
    __shared__ int   shc[8];
    const int lane = threadIdx.x & 31;
    const int wid  = threadIdx.x >> 5;
    if (lane == 0) { sh0[wid] = s0; sh1[wid] = s1; shc[wid] = c1; }
    __syncthreads();

    __shared__ bool is_last;
    if (wid == 0) {
        const int nw = blockDim.x >> 5;
        s0 = (lane < nw) ? sh0[lane] : 0.0f;
        s1 = (lane < nw) ? sh1[lane] : 0.0f;
        c1 = (lane < nw) ? shc[lane] : 0;
        #pragma unroll
        for (int off = 4; off > 0; off >>= 1) {
            s0 += __shfl_down_sync(0xFFFFFFFFu, s0, off);
            s1 += __shfl_down_sync(0xFFFFFFFFu, s1, off);
            c1 += __shfl_down_sync(0xFFFFFFFFu, c1, off);
        }
        if (lane == 0) {
            atomicAdd(&g_sum0, (double)s0);
            atomicAdd(&g_sum1, (double)s1);
            atomicAdd(&g_cnt1, (unsigned long long)c1);
            __threadfence();
            unsigned int done = atomicAdd(&g_blocks_done, 1u);
            is_last = (done == gridDim.x - 1u);
        }
    }
    __syncthreads();

    // Last block to retire finalizes and resets globals for the next replay.
    if (is_last && threadIdx.x == 0) {
        __threadfence();
        double sum0 = g_sum0;
        double sum1 = g_sum1;
        unsigned long long n1 = g_cnt1;
        unsigned long long n0 = (unsigned long long)n_tokens - n1;
        double r = (n1 > 0) ? (-sum1 / (double)n1) : 0.0;
        double p = (n0 > 0) ? (-sum0 / (double)n0) : 0.0;
        out[0] = (float)(p + r);
        // reset for next graph replay
        g_sum0 = 0.0;
        g_sum1 = 0.0;
        g_cnt1 = 0ull;
        g_blocks_done = 0u;
    }
}

extern "C" void kernel_launch(void* const* d_in, const int* in_sizes, int n_in,
                              void* d_out, int out_size) {
    const float* x       = (const float*)d_in[0];
    const int*   targets = (const int*)d_in[1];
    float*       out     = (float*)d_out;

    const long long n_tokens = (long long)in_sizes[1];

    const long long threads_needed = (n_tokens + 7) / 8;
    const int block = 256;
    const int grid  = (int)((threads_needed + block - 1) / block);
    nll_fused_kernel<<<grid, block>>>(x, targets, n_tokens, out);
}